// round 7
// baseline (speedup 1.0000x reference)
#include <cuda_runtime.h>
#include <math.h>
#include <stdint.h>

#define NNODES 50000
#define NEDGES 800000
#define DIM    128
#define NGRAPH 64
#define ETOT   (NEDGES + NNODES)
#define NEG_SLOPE 0.2f
#define TILES  ((NNODES + 127) / 128)
#define GEMM_GRID 148

// ---------------- scratch (device globals; no allocation allowed) ----------------
__device__ float g_h [NNODES * DIM];
__device__ float g_f1[NNODES * DIM];
__device__ float g_as[NNODES];
__device__ float g_ad[NNODES];
__device__ int   g_deg   [NNODES];
__device__ int   g_rowptr[NNODES + 1];
__device__ int   g_rank  [ETOT];
__device__ int   g_csrc  [ETOT];

// ---------------- helpers ----------------
__device__ __forceinline__ float tf32r(float x) {   // round-to-nearest tf32
    uint32_t u;
    asm("cvt.rna.tf32.f32 %0, %1;" : "=r"(u) : "f"(x));
    return __uint_as_float(u);
}

__device__ __forceinline__ void mma_tf32(float* c, const uint32_t* a, uint32_t b0, uint32_t b1) {
    asm volatile("mma.sync.aligned.m16n8k8.row.col.f32.tf32.tf32.f32 "
                 "{%0,%1,%2,%3}, {%4,%5,%6,%7}, {%8,%9}, {%0,%1,%2,%3};"
                 : "+f"(c[0]), "+f"(c[1]), "+f"(c[2]), "+f"(c[3])
                 : "r"(a[0]), "r"(a[1]), "r"(a[2]), "r"(a[3]), "r"(b0), "r"(b1));
}

// smem geometry (float2 pitches chosen for conflict-free fragment loads)
#define PA 68
#define PB 132
struct SmemGemm {
    float2 A[128 * PA];
    float2 B[128 * PB];
    float  asrc[128];
    float  adst[128];
};
#define SM_TOTAL ((int)sizeof(SmemGemm))

// ---------------- CSR build (3 kernels) ----------------
__global__ void k_init(float* __restrict__ pooled) {
    int i = blockIdx.x * blockDim.x + threadIdx.x;
    if (i < NNODES) g_deg[i] = 0;
    if (i < NGRAPH * DIM) pooled[i] = 0.f;
}

// histogram + rank recording (edges then self-loops)
__global__ void k_hist(const int* __restrict__ ei) {
    int e = blockIdx.x * blockDim.x + threadIdx.x;
    if (e < NEDGES) {
        int dst = ei[NEDGES + e];
        g_rank[e] = atomicAdd(&g_deg[dst], 1);
    } else if (e < ETOT) {
        int v = e - NEDGES;
        g_rank[e] = atomicAdd(&g_deg[v], 1);
    }
}

// single-block exclusive scan of deg -> rowptr (1024 threads, 49 elems each)
#define SCAN_PER 49
__global__ __launch_bounds__(1024) void k_scan() {
    __shared__ int sh[1024];
    int tid = threadIdx.x;
    int base = tid * SCAN_PER;
    // pass 1: per-thread total
    int s = 0;
#pragma unroll 7
    for (int j = 0; j < SCAN_PER; j++) {
        int i = base + j;
        if (i < NNODES) s += g_deg[i];
    }
    sh[tid] = s;
    __syncthreads();
    // Hillis-Steele inclusive scan over 1024 totals
    for (int o = 1; o < 1024; o <<= 1) {
        int t = (tid >= o) ? sh[tid - o] : 0;
        __syncthreads();
        sh[tid] += t;
        __syncthreads();
    }
    int run = sh[tid] - s;     // exclusive prefix for this thread's range
    // pass 2: write exclusive prefixes
#pragma unroll 7
    for (int j = 0; j < SCAN_PER; j++) {
        int i = base + j;
        if (i < NNODES) {
            g_rowptr[i] = run;
            run += g_deg[i];
        }
    }
    if (tid == 1023) g_rowptr[NNODES] = ETOT;
}

// atomic-free placement using precomputed ranks
__global__ void k_place(const int* __restrict__ ei) {
    int e = blockIdx.x * blockDim.x + threadIdx.x;
    if (e < NEDGES) {
        int src = ei[e];
        int dst = ei[NEDGES + e];
        g_csrc[g_rowptr[dst] + g_rank[e]] = src;
    } else if (e < ETOT) {
        int v = e - NEDGES;
        g_csrc[g_rowptr[v] + g_rank[e]] = v;
    }
}

// ---------------- 3xTF32 mma.sync GEMM + fused alpha dots ----------------
__global__ __launch_bounds__(256, 1) void k_gemm_mma(const float* __restrict__ xin, int layer,
                                                     const float* __restrict__ W,
                                                     const float* __restrict__ a_src,
                                                     const float* __restrict__ a_dst) {
    extern __shared__ char smraw[];
    SmemGemm* sm = (SmemGemm*)smraw;
    const float* __restrict__ A = layer ? g_f1 : xin;

    int tid = threadIdx.x;
    int lane = tid & 31;
    int gq = lane >> 2;
    int tq = lane & 3;
    int m0 = (tid >> 5) * 16;

    for (int e = tid; e < 16384; e += 256) {
        int k = e >> 7, n = e & 127;
        float v = W[e];
        float hi = tf32r(v);
        float lo = tf32r(v - hi);
        sm->B[k * PB + n] = make_float2(hi, lo);
    }
    if (tid < 128) { sm->asrc[tid] = a_src[tid]; sm->adst[tid] = a_dst[tid]; }
    __syncthreads();

    for (int tile = blockIdx.x; tile < TILES; tile += GEMM_GRID) {
        int row0 = tile * 128;
        float acc[16][4];
#pragma unroll
        for (int j = 0; j < 16; j++)
#pragma unroll
            for (int q = 0; q < 4; q++) acc[j][q] = 0.f;

        for (int half = 0; half < 2; half++) {
            __syncthreads();
#pragma unroll
            for (int i = 0; i < 8; i++) {
                int f4 = i * 256 + tid;
                int row = f4 >> 4;
                int c4 = (f4 & 15) * 4;
                int gr = row0 + row;
                float4 v = make_float4(0.f, 0.f, 0.f, 0.f);
                if (gr < NNODES) v = *(const float4*)&A[gr * 128 + half * 64 + c4];
                float h0 = tf32r(v.x), h1 = tf32r(v.y), h2 = tf32r(v.z), h3 = tf32r(v.w);
                sm->A[row * PA + c4 + 0] = make_float2(h0, tf32r(v.x - h0));
                sm->A[row * PA + c4 + 1] = make_float2(h1, tf32r(v.y - h1));
                sm->A[row * PA + c4 + 2] = make_float2(h2, tf32r(v.z - h2));
                sm->A[row * PA + c4 + 3] = make_float2(h3, tf32r(v.w - h3));
            }
            __syncthreads();

#pragma unroll
            for (int ks = 0; ks < 8; ks++) {
                int kl = ks * 8;
                float2 fa0 = sm->A[(m0 + gq) * PA + kl + tq];
                float2 fa1 = sm->A[(m0 + gq + 8) * PA + kl + tq];
                float2 fa2 = sm->A[(m0 + gq) * PA + kl + tq + 4];
                float2 fa3 = sm->A[(m0 + gq + 8) * PA + kl + tq + 4];
                uint32_t ahi[4] = { __float_as_uint(fa0.x), __float_as_uint(fa1.x),
                                    __float_as_uint(fa2.x), __float_as_uint(fa3.x) };
                uint32_t alo[4] = { __float_as_uint(fa0.y), __float_as_uint(fa1.y),
                                    __float_as_uint(fa2.y), __float_as_uint(fa3.y) };
                int kb = (half * 64 + kl + tq) * PB + gq;
#pragma unroll
                for (int j = 0; j < 16; j++) {
                    float2 b0 = sm->B[kb + 8 * j];
                    float2 b1 = sm->B[kb + 4 * PB + 8 * j];
                    uint32_t bh0 = __float_as_uint(b0.x), bh1 = __float_as_uint(b1.x);
                    uint32_t bl0 = __float_as_uint(b0.y), bl1 = __float_as_uint(b1.y);
                    mma_tf32(acc[j], ahi, bh0, bh1);
                    mma_tf32(acc[j], ahi, bl0, bl1);
                    mma_tf32(acc[j], alo, bh0, bh1);
                }
            }
        }

        int r1 = row0 + m0 + gq;
        int r2 = r1 + 8;
        float ps1 = 0.f, pd1 = 0.f, ps2 = 0.f, pd2 = 0.f;
#pragma unroll
        for (int j = 0; j < 16; j++) {
            int c0 = 8 * j + 2 * tq;
            if (r1 < NNODES) *(float2*)&g_h[r1 * 128 + c0] = make_float2(acc[j][0], acc[j][1]);
            if (r2 < NNODES) *(float2*)&g_h[r2 * 128 + c0] = make_float2(acc[j][2], acc[j][3]);
            float s0 = sm->asrc[c0], s1 = sm->asrc[c0 + 1];
            float d0 = sm->adst[c0], d1 = sm->adst[c0 + 1];
            ps1 += acc[j][0] * s0 + acc[j][1] * s1;
            pd1 += acc[j][0] * d0 + acc[j][1] * d1;
            ps2 += acc[j][2] * s0 + acc[j][3] * s1;
            pd2 += acc[j][2] * d0 + acc[j][3] * d1;
        }
#pragma unroll
        for (int o = 1; o <= 2; o <<= 1) {
            ps1 += __shfl_xor_sync(0xffffffff, ps1, o);
            pd1 += __shfl_xor_sync(0xffffffff, pd1, o);
            ps2 += __shfl_xor_sync(0xffffffff, ps2, o);
            pd2 += __shfl_xor_sync(0xffffffff, pd2, o);
        }
        if (tq == 0) {
            if (r1 < NNODES) { g_as[r1] = ps1; g_ad[r1] = pd1; }
            if (r2 < NNODES) { g_as[r2] = ps2; g_ad[r2] = pd2; }
        }
    }
}

// ---------------- per-node softmax + aggregation: warp-per-node, float4 lanes ----------------
#define AGG_WARPS 8
#define WCAP 64
__global__ __launch_bounds__(256) void k_aggregate(const float* __restrict__ bias,
                                                   float* __restrict__ dout, int to_f1) {
    __shared__ float2 cache[AGG_WARPS][WCAP];   // (exp(e), src bits)

    int w = threadIdx.x >> 5;
    int lane = threadIdx.x & 31;
    int v = blockIdx.x * AGG_WARPS + w;
    if (v >= NNODES) return;

    int base = g_rowptr[v];
    int deg = g_rowptr[v + 1] - base;
    float ad = g_ad[v];
    int n1 = (deg < WCAP) ? deg : WCAP;

    float lsum = 0.f;
    for (int i = lane; i < n1; i += 32) {
        int s = g_csrc[base + i];
        float e = g_as[s] + ad;
        e = (e > 0.f) ? e : NEG_SLOPE * e;
        float ex = __expf(e);
        cache[w][i] = make_float2(ex, __int_as_float(s));
        lsum += ex;
    }
    for (int i = WCAP + lane; i < deg; i += 32) {   // rare overflow path
        int s = g_csrc[base + i];
        float e = g_as[s] + ad;
        e = (e > 0.f) ? e : NEG_SLOPE * e;
        lsum += __expf(e);
    }
#pragma unroll
    for (int o = 16; o > 0; o >>= 1) lsum += __shfl_xor_sync(0xffffffff, lsum, o);
    float scale = 1.f / (lsum + 1e-16f);
    __syncwarp();

    float4 acc = make_float4(0.f, 0.f, 0.f, 0.f);
#pragma unroll 4
    for (int j = 0; j < n1; j++) {
        float2 c = cache[w][j];
        int s = __float_as_int(c.y);
        float4 hv = *(const float4*)&g_h[s * 128 + lane * 4];
        acc.x += hv.x * c.x; acc.y += hv.y * c.x;
        acc.z += hv.z * c.x; acc.w += hv.w * c.x;
    }
    for (int j = WCAP; j < deg; j++) {              // rare overflow path
        int s = g_csrc[base + j];
        float e = g_as[s] + ad;
        e = (e > 0.f) ? e : NEG_SLOPE * e;
        float ex = __expf(e);
        float4 hv = *(const float4*)&g_h[s * 128 + lane * 4];
        acc.x += hv.x * ex; acc.y += hv.y * ex;
        acc.z += hv.z * ex; acc.w += hv.w * ex;
    }
    float4 b4 = *(const float4*)&bias[lane * 4];
    float* out = to_f1 ? g_f1 : dout;
    *(float4*)&out[v * 128 + lane * 4] = make_float4(
        b4.x + acc.x * scale, b4.y + acc.y * scale,
        b4.z + acc.z * scale, b4.w + acc.w * scale);
}

// ---------------- global mean pool ----------------
__device__ __forceinline__ int lbound(const int* a, int n, int key) {
    int lo = 0, hi = n;
    while (lo < hi) { int mid = (lo + hi) >> 1; if (a[mid] < key) lo = mid + 1; else hi = mid; }
    return lo;
}
#define POOL_CHUNKS 8
__global__ void k_pool(const float* __restrict__ feats, const int* __restrict__ batch,
                       float* __restrict__ pooled) {
    int g = blockIdx.x;
    int c = blockIdx.y;
    int tid = threadIdx.x;
    int lo = lbound(batch, NNODES, g);
    int hi = lbound(batch, NNODES, g + 1);
    int cnt = hi - lo;
    if (cnt <= 0) return;
    float acc = 0.f;
    for (int n = lo + c; n < hi; n += POOL_CHUNKS) acc += feats[n * 128 + tid];
    atomicAdd(&pooled[g * 128 + tid], acc / (float)cnt);
}

// ---------------- launch ----------------
extern "C" void kernel_launch(void* const* d_in, const int* in_sizes, int n_in,
                              void* d_out, int out_size) {
    const float* x   = (const float*)d_in[0];
    const int*   ei  = (const int*)d_in[1];
    const int*   bat = (const int*)d_in[2];
    const float* W1  = (const float*)d_in[3];
    const float* as1 = (const float*)d_in[4];
    const float* ad1 = (const float*)d_in[5];
    const float* b1  = (const float*)d_in[6];
    const float* W2  = (const float*)d_in[7];
    const float* as2 = (const float*)d_in[8];
    const float* ad2 = (const float*)d_in[9];
    const float* b2  = (const float*)d_in[10];
    float* out = (float*)d_out;
    float* pooled = out + NNODES * DIM;

    static cudaStream_t s2 = nullptr;
    static cudaEvent_t ev_fork = nullptr, ev_csr = nullptr;
    if (s2 == nullptr) {
        cudaStreamCreateWithFlags(&s2, cudaStreamNonBlocking);
        cudaEventCreateWithFlags(&ev_fork, cudaEventDisableTiming);
        cudaEventCreateWithFlags(&ev_csr, cudaEventDisableTiming);
        cudaFuncSetAttribute(k_gemm_mma, cudaFuncAttributeMaxDynamicSharedMemorySize, SM_TOTAL);
    }

    // fork: CSR build (+pooled zero) on s2, overlapping layer-1 GEMM
    cudaEventRecord(ev_fork, 0);
    cudaStreamWaitEvent(s2, ev_fork, 0);
    k_init<<<(NNODES + 255) / 256, 256, 0, s2>>>(pooled);
    k_hist<<<(ETOT + 255) / 256, 256, 0, s2>>>(ei);
    k_scan<<<1, 1024, 0, s2>>>();
    k_place<<<(ETOT + 255) / 256, 256, 0, s2>>>(ei);
    cudaEventRecord(ev_csr, s2);

    int aggBlocks = (NNODES + AGG_WARPS - 1) / AGG_WARPS;

    // layer 1
    k_gemm_mma<<<GEMM_GRID, 256, SM_TOTAL>>>(x, 0, W1, as1, ad1);
    cudaStreamWaitEvent(0, ev_csr, 0);
    k_aggregate<<<aggBlocks, 256>>>(b1, out, 1);

    // layer 2
    k_gemm_mma<<<GEMM_GRID, 256, SM_TOTAL>>>(x, 1, W2, as2, ad2);
    k_aggregate<<<aggBlocks, 256>>>(b2, out, 0);

    // pool
    dim3 pg(NGRAPH, POOL_CHUNKS);
    k_pool<<<pg, 128>>>(out, bat, pooled);
}

// round 8
// speedup vs baseline: 1.4839x; 1.4839x over previous
#include <cuda_runtime.h>
#include <math.h>
#include <stdint.h>

#define NNODES 50000
#define NEDGES 800000
#define DIM    128
#define NGRAPH 64
#define ETOT   (NEDGES + NNODES)
#define SCAN_B 1024
#define NSCAN  ((NNODES + SCAN_B - 1) / SCAN_B)
#define NEG_SLOPE 0.2f
#define TILES  ((NNODES + 127) / 128)
#define GEMM_GRID 148

// ---------------- scratch (device globals; no allocation allowed) ----------------
__device__ float g_h [NNODES * DIM];
__device__ float g_f1[NNODES * DIM];
__device__ float g_as[NNODES];
__device__ float g_ad[NNODES];
__device__ int   g_deg   [NNODES];
__device__ int   g_rowptr[NNODES + 1];
__device__ int   g_cursor[NNODES];
__device__ int   g_csrc  [ETOT];
__device__ int   g_bsum  [NSCAN];

// ---------------- helpers ----------------
__device__ __forceinline__ float tf32r(float x) {   // round-to-nearest tf32
    uint32_t u;
    asm("cvt.rna.tf32.f32 %0, %1;" : "=r"(u) : "f"(x));
    return __uint_as_float(u);
}

__device__ __forceinline__ void mma_tf32(float* c, const uint32_t* a, uint32_t b0, uint32_t b1) {
    asm volatile("mma.sync.aligned.m16n8k8.row.col.f32.tf32.tf32.f32 "
                 "{%0,%1,%2,%3}, {%4,%5,%6,%7}, {%8,%9}, {%0,%1,%2,%3};"
                 : "+f"(c[0]), "+f"(c[1]), "+f"(c[2]), "+f"(c[3])
                 : "r"(a[0]), "r"(a[1]), "r"(a[2]), "r"(a[3]), "r"(b0), "r"(b1));
}

// smem geometry (float2 pitches chosen for conflict-free fragment loads)
#define PA 68
#define PB 132
struct SmemGemm {
    float2 A[128 * PA];
    float2 B[128 * PB];
    float  asrc[128];
    float  adst[128];
};
#define SM_TOTAL ((int)sizeof(SmemGemm))

// ---------------- CSR build ----------------
__global__ void k_initdeg(float* __restrict__ pooled) {
    int i = blockIdx.x * blockDim.x + threadIdx.x;
    if (i < NNODES) g_deg[i] = 1;              // self-loop
    if (i < NGRAPH * DIM) pooled[i] = 0.f;     // fused pooled zeroing
}
__global__ void k_hist(const int* __restrict__ ei) {
    int e = blockIdx.x * blockDim.x + threadIdx.x;
    if (e < NEDGES) atomicAdd(&g_deg[ei[NEDGES + e]], 1);
}
__global__ void k_scan1() {
    __shared__ int sh[SCAN_B];
    int tid = threadIdx.x;
    int i = blockIdx.x * SCAN_B + tid;
    int v = (i < NNODES) ? g_deg[i] : 0;
    sh[tid] = v;
    __syncthreads();
    for (int o = 1; o < SCAN_B; o <<= 1) {
        int t = (tid >= o) ? sh[tid - o] : 0;
        __syncthreads();
        sh[tid] += t;
        __syncthreads();
    }
    if (i < NNODES) g_rowptr[i] = sh[tid] - v;
    if (tid == SCAN_B - 1) g_bsum[blockIdx.x] = sh[tid];
}
// scan3 now folds the tiny 49-entry block-sum prefix locally (removes serial k_scan2)
__global__ void k_scan3() {
    __shared__ int pre[NSCAN];
    int tid = threadIdx.x;
    if (tid < NSCAN) pre[tid] = g_bsum[tid];
    __syncthreads();
    if (tid == 0) {
        int acc = 0;
        for (int b = 0; b < NSCAN; b++) { int t = pre[b]; pre[b] = acc; acc += t; }
    }
    __syncthreads();
    int i = blockIdx.x * blockDim.x + tid;
    if (i < NNODES) {
        int r = g_rowptr[i] + pre[i / SCAN_B];
        g_rowptr[i] = r;
        g_cursor[i] = r;
    }
    if (i == 0) g_rowptr[NNODES] = ETOT;
}
__global__ void k_scatter(const int* __restrict__ ei) {
    int e = blockIdx.x * blockDim.x + threadIdx.x;
    if (e < NEDGES) {
        int src = ei[e];
        int dst = ei[NEDGES + e];
        g_csrc[atomicAdd(&g_cursor[dst], 1)] = src;
    } else if (e < ETOT) {
        int v = e - NEDGES;
        g_csrc[atomicAdd(&g_cursor[v], 1)] = v;
    }
}

// ---------------- 3xTF32 mma.sync GEMM + fused alpha dots ----------------
__global__ __launch_bounds__(256, 1) void k_gemm_mma(const float* __restrict__ xin, int layer,
                                                     const float* __restrict__ W,
                                                     const float* __restrict__ a_src,
                                                     const float* __restrict__ a_dst) {
    extern __shared__ char smraw[];
    SmemGemm* sm = (SmemGemm*)smraw;
    const float* __restrict__ A = layer ? g_f1 : xin;

    int tid = threadIdx.x;
    int lane = tid & 31;
    int gq = lane >> 2;
    int tq = lane & 3;
    int m0 = (tid >> 5) * 16;

    for (int e = tid; e < 16384; e += 256) {
        int k = e >> 7, n = e & 127;
        float v = W[e];
        float hi = tf32r(v);
        float lo = tf32r(v - hi);
        sm->B[k * PB + n] = make_float2(hi, lo);
    }
    if (tid < 128) { sm->asrc[tid] = a_src[tid]; sm->adst[tid] = a_dst[tid]; }
    __syncthreads();

    for (int tile = blockIdx.x; tile < TILES; tile += GEMM_GRID) {
        int row0 = tile * 128;
        float acc[16][4];
#pragma unroll
        for (int j = 0; j < 16; j++)
#pragma unroll
            for (int q = 0; q < 4; q++) acc[j][q] = 0.f;

        for (int half = 0; half < 2; half++) {
            __syncthreads();
#pragma unroll
            for (int i = 0; i < 8; i++) {
                int f4 = i * 256 + tid;
                int row = f4 >> 4;
                int c4 = (f4 & 15) * 4;
                int gr = row0 + row;
                float4 v = make_float4(0.f, 0.f, 0.f, 0.f);
                if (gr < NNODES) v = *(const float4*)&A[gr * 128 + half * 64 + c4];
                float h0 = tf32r(v.x), h1 = tf32r(v.y), h2 = tf32r(v.z), h3 = tf32r(v.w);
                sm->A[row * PA + c4 + 0] = make_float2(h0, tf32r(v.x - h0));
                sm->A[row * PA + c4 + 1] = make_float2(h1, tf32r(v.y - h1));
                sm->A[row * PA + c4 + 2] = make_float2(h2, tf32r(v.z - h2));
                sm->A[row * PA + c4 + 3] = make_float2(h3, tf32r(v.w - h3));
            }
            __syncthreads();

#pragma unroll
            for (int ks = 0; ks < 8; ks++) {
                int kl = ks * 8;
                float2 fa0 = sm->A[(m0 + gq) * PA + kl + tq];
                float2 fa1 = sm->A[(m0 + gq + 8) * PA + kl + tq];
                float2 fa2 = sm->A[(m0 + gq) * PA + kl + tq + 4];
                float2 fa3 = sm->A[(m0 + gq + 8) * PA + kl + tq + 4];
                uint32_t ahi[4] = { __float_as_uint(fa0.x), __float_as_uint(fa1.x),
                                    __float_as_uint(fa2.x), __float_as_uint(fa3.x) };
                uint32_t alo[4] = { __float_as_uint(fa0.y), __float_as_uint(fa1.y),
                                    __float_as_uint(fa2.y), __float_as_uint(fa3.y) };
                int kb = (half * 64 + kl + tq) * PB + gq;
#pragma unroll
                for (int j = 0; j < 16; j++) {
                    float2 b0 = sm->B[kb + 8 * j];
                    float2 b1 = sm->B[kb + 4 * PB + 8 * j];
                    uint32_t bh0 = __float_as_uint(b0.x), bh1 = __float_as_uint(b1.x);
                    uint32_t bl0 = __float_as_uint(b0.y), bl1 = __float_as_uint(b1.y);
                    mma_tf32(acc[j], ahi, bh0, bh1);
                    mma_tf32(acc[j], ahi, bl0, bl1);
                    mma_tf32(acc[j], alo, bh0, bh1);
                }
            }
        }

        int r1 = row0 + m0 + gq;
        int r2 = r1 + 8;
        float ps1 = 0.f, pd1 = 0.f, ps2 = 0.f, pd2 = 0.f;
#pragma unroll
        for (int j = 0; j < 16; j++) {
            int c0 = 8 * j + 2 * tq;
            if (r1 < NNODES) *(float2*)&g_h[r1 * 128 + c0] = make_float2(acc[j][0], acc[j][1]);
            if (r2 < NNODES) *(float2*)&g_h[r2 * 128 + c0] = make_float2(acc[j][2], acc[j][3]);
            float s0 = sm->asrc[c0], s1 = sm->asrc[c0 + 1];
            float d0 = sm->adst[c0], d1 = sm->adst[c0 + 1];
            ps1 += acc[j][0] * s0 + acc[j][1] * s1;
            pd1 += acc[j][0] * d0 + acc[j][1] * d1;
            ps2 += acc[j][2] * s0 + acc[j][3] * s1;
            pd2 += acc[j][2] * d0 + acc[j][3] * d1;
        }
#pragma unroll
        for (int o = 1; o <= 2; o <<= 1) {
            ps1 += __shfl_xor_sync(0xffffffff, ps1, o);
            pd1 += __shfl_xor_sync(0xffffffff, pd1, o);
            ps2 += __shfl_xor_sync(0xffffffff, ps2, o);
            pd2 += __shfl_xor_sync(0xffffffff, pd2, o);
        }
        if (tq == 0) {
            if (r1 < NNODES) { g_as[r1] = ps1; g_ad[r1] = pd1; }
            if (r2 < NNODES) { g_as[r2] = ps2; g_ad[r2] = pd2; }
        }
    }
}

// ---------------- per-node softmax + aggregation: warp-per-node, float4 lanes ----------------
#define AGG_WARPS 8
#define WCAP 64
__global__ __launch_bounds__(256) void k_aggregate(const float* __restrict__ bias,
                                                   float* __restrict__ dout, int to_f1) {
    __shared__ float2 cache[AGG_WARPS][WCAP];   // (exp(e), src bits)

    int w = threadIdx.x >> 5;
    int lane = threadIdx.x & 31;
    int v = blockIdx.x * AGG_WARPS + w;
    if (v >= NNODES) return;

    int base = g_rowptr[v];
    int deg = g_rowptr[v + 1] - base;
    float ad = g_ad[v];
    int n1 = (deg < WCAP) ? deg : WCAP;

    float lsum = 0.f;
    for (int i = lane; i < n1; i += 32) {
        int s = g_csrc[base + i];
        float e = g_as[s] + ad;
        e = (e > 0.f) ? e : NEG_SLOPE * e;
        float ex = __expf(e);
        cache[w][i] = make_float2(ex, __int_as_float(s));
        lsum += ex;
    }
    for (int i = WCAP + lane; i < deg; i += 32) {   // rare overflow path
        int s = g_csrc[base + i];
        float e = g_as[s] + ad;
        e = (e > 0.f) ? e : NEG_SLOPE * e;
        lsum += __expf(e);
    }
#pragma unroll
    for (int o = 16; o > 0; o >>= 1) lsum += __shfl_xor_sync(0xffffffff, lsum, o);
    float scale = 1.f / (lsum + 1e-16f);
    __syncwarp();

    float4 acc = make_float4(0.f, 0.f, 0.f, 0.f);
#pragma unroll 4
    for (int j = 0; j < n1; j++) {
        float2 c = cache[w][j];
        int s = __float_as_int(c.y);
        float4 hv = *(const float4*)&g_h[s * 128 + lane * 4];
        acc.x += hv.x * c.x; acc.y += hv.y * c.x;
        acc.z += hv.z * c.x; acc.w += hv.w * c.x;
    }
    for (int j = WCAP; j < deg; j++) {              // rare overflow path
        int s = g_csrc[base + j];
        float e = g_as[s] + ad;
        e = (e > 0.f) ? e : NEG_SLOPE * e;
        float ex = __expf(e);
        float4 hv = *(const float4*)&g_h[s * 128 + lane * 4];
        acc.x += hv.x * ex; acc.y += hv.y * ex;
        acc.z += hv.z * ex; acc.w += hv.w * ex;
    }
    float4 b4 = *(const float4*)&bias[lane * 4];
    float* out = to_f1 ? g_f1 : dout;
    *(float4*)&out[v * 128 + lane * 4] = make_float4(
        b4.x + acc.x * scale, b4.y + acc.y * scale,
        b4.z + acc.z * scale, b4.w + acc.w * scale);
}

// ---------------- global mean pool ----------------
__device__ __forceinline__ int lbound(const int* a, int n, int key) {
    int lo = 0, hi = n;
    while (lo < hi) { int mid = (lo + hi) >> 1; if (a[mid] < key) lo = mid + 1; else hi = mid; }
    return lo;
}
#define POOL_CHUNKS 8
__global__ void k_pool(const float* __restrict__ feats, const int* __restrict__ batch,
                       float* __restrict__ pooled) {
    int g = blockIdx.x;
    int c = blockIdx.y;
    int tid = threadIdx.x;
    int lo = lbound(batch, NNODES, g);
    int hi = lbound(batch, NNODES, g + 1);
    int cnt = hi - lo;
    if (cnt <= 0) return;
    float acc = 0.f;
    for (int n = lo + c; n < hi; n += POOL_CHUNKS) acc += feats[n * 128 + tid];
    atomicAdd(&pooled[g * 128 + tid], acc / (float)cnt);
}

// ---------------- launch ----------------
extern "C" void kernel_launch(void* const* d_in, const int* in_sizes, int n_in,
                              void* d_out, int out_size) {
    const float* x   = (const float*)d_in[0];
    const int*   ei  = (const int*)d_in[1];
    const int*   bat = (const int*)d_in[2];
    const float* W1  = (const float*)d_in[3];
    const float* as1 = (const float*)d_in[4];
    const float* ad1 = (const float*)d_in[5];
    const float* b1  = (const float*)d_in[6];
    const float* W2  = (const float*)d_in[7];
    const float* as2 = (const float*)d_in[8];
    const float* ad2 = (const float*)d_in[9];
    const float* b2  = (const float*)d_in[10];
    float* out = (float*)d_out;
    float* pooled = out + NNODES * DIM;

    static cudaStream_t s2 = nullptr;
    static cudaEvent_t ev_fork = nullptr, ev_csr = nullptr;
    if (s2 == nullptr) {
        cudaStreamCreateWithFlags(&s2, cudaStreamNonBlocking);
        cudaEventCreateWithFlags(&ev_fork, cudaEventDisableTiming);
        cudaEventCreateWithFlags(&ev_csr, cudaEventDisableTiming);
        cudaFuncSetAttribute(k_gemm_mma, cudaFuncAttributeMaxDynamicSharedMemorySize, SM_TOTAL);
    }

    // fork: CSR build (+pooled zeroing) on s2, overlapping layer-1 GEMM
    cudaEventRecord(ev_fork, 0);
    cudaStreamWaitEvent(s2, ev_fork, 0);
    k_initdeg<<<(NNODES + 255) / 256, 256, 0, s2>>>(pooled);
    k_hist<<<(NEDGES + 255) / 256, 256, 0, s2>>>(ei);
    k_scan1<<<NSCAN, SCAN_B, 0, s2>>>();
    k_scan3<<<(NNODES + 255) / 256, 256, 0, s2>>>();
    k_scatter<<<(ETOT + 255) / 256, 256, 0, s2>>>(ei);
    cudaEventRecord(ev_csr, s2);

    int aggBlocks = (NNODES + AGG_WARPS - 1) / AGG_WARPS;

    // layer 1
    k_gemm_mma<<<GEMM_GRID, 256, SM_TOTAL>>>(x, 0, W1, as1, ad1);
    cudaStreamWaitEvent(0, ev_csr, 0);
    k_aggregate<<<aggBlocks, 256>>>(b1, out, 1);

    // layer 2
    k_gemm_mma<<<GEMM_GRID, 256, SM_TOTAL>>>(x, 1, W2, as2, ad2);
    k_aggregate<<<aggBlocks, 256>>>(b2, out, 0);

    // pool
    dim3 pg(NGRAPH, POOL_CHUNKS);
    k_pool<<<pg, 128>>>(out, bat, pooled);
}